// round 17
// baseline (speedup 1.0000x reference)
#include <cuda_runtime.h>
#include <cuda_bf16.h>
#include <math.h>
#include <stdint.h>

// Problem constants: B=1, C=256, H=W=96
#define C_DIM 256
#define HDIM  96
#define HW    9216          // H*W
#define CW    24576         // C*W
#define NPIX  (C_DIM*HW)    // 2359296

// ---------------------------------------------------------------------------
// Device-global scratch. bf16 split hi/lo, packed bf16x2 (uint32).
__device__ uint32_t g_FQh[NPIX/2], g_FQl[NPIX/2];   // FQ hi/lo [c][p/2]
__device__ uint32_t g_Wh0[32768], g_Wl0[32768];     // Wq hi/lo [o][c/2]
__device__ uint32_t g_Wh1[32768], g_Wl1[32768];     // Wv hi/lo [o][c/2]
__device__ float    g_FQM[CW];                      // Fuse_Q_mask

// ---------------------------------------------------------------------------
__device__ __forceinline__ void atomicMaxFloat(float* addr, float val) {
    if (val >= 0.0f) atomicMax((int*)addr, __float_as_int(val));
    else             atomicMin((unsigned int*)addr, __float_as_uint(val));
}

__device__ __forceinline__ uint32_t pack_bf2(float a, float b) {
    __nv_bfloat16 ha = __float2bfloat16_rn(a);
    __nv_bfloat16 hb = __float2bfloat16_rn(b);
    unsigned short ua = *reinterpret_cast<unsigned short*>(&ha);
    unsigned short ub = *reinterpret_cast<unsigned short*>(&hb);
    return (uint32_t)ua | ((uint32_t)ub << 16);
}
__device__ __forceinline__ float bf_hi_val(float a) {
    __nv_bfloat16 h = __float2bfloat16_rn(a);
    return __bfloat162float(h);
}

__device__ __forceinline__ void cp_async16(uint32_t dst, const void* src) {
    asm volatile("cp.async.cg.shared.global [%0], [%1], 16;\n" :: "r"(dst), "l"(src));
}
#define CP_ASYNC_COMMIT() asm volatile("cp.async.commit_group;\n")
#define CP_ASYNC_WAIT0()  asm volatile("cp.async.wait_group 0;\n")

// m16n8k16 bf16 MMA, fp32 accumulate (standard PTX, compiles on plain sm_103)
__device__ __forceinline__ void mma16816(float* d, const uint32_t* a,
                                         const uint32_t* b) {
    asm volatile(
        "mma.sync.aligned.m16n8k16.row.col.f32.bf16.bf16.f32 "
        "{%0,%1,%2,%3}, {%4,%5,%6,%7}, {%8,%9}, {%0,%1,%2,%3};"
        : "+f"(d[0]), "+f"(d[1]), "+f"(d[2]), "+f"(d[3])
        : "r"(a[0]), "r"(a[1]), "r"(a[2]), "r"(a[3]), "r"(b[0]), "r"(b[1]));
}

// ---------------------------------------------------------------------------
// Convert Wq, Wv to split bf16 hi/lo (row-major [o][c/2]).
__global__ __launch_bounds__(256) void convert_w(
    const float* __restrict__ Wq, const float* __restrict__ Wv)
{
    unsigned v = blockIdx.x * 256u + threadIdx.x;   // float4 index
    const float* src; uint32_t *dh, *dl; unsigned base;
    if (v < 16384)      { src = Wq; dh = g_Wh0; dl = g_Wl0; base = v; }
    else if (v < 32768) { src = Wv; dh = g_Wh1; dl = g_Wl1; base = v - 16384; }
    else return;
    float4 x = ((const float4*)src)[base];
    float h0 = bf_hi_val(x.x), h1 = bf_hi_val(x.y);
    float h2 = bf_hi_val(x.z), h3 = bf_hi_val(x.w);
    dh[2*base]   = pack_bf2(x.x, x.y);
    dh[2*base+1] = pack_bf2(x.z, x.w);
    dl[2*base]   = pack_bf2(x.x - h0, x.y - h1);
    dl[2*base+1] = pack_bf2(x.z - h2, x.w - h3);
}

// ---------------------------------------------------------------------------
// Per-channel frequency filter (proven R15/R16): conflict-free smem (pitch 97),
// conjugate symmetry. Emits FQ directly as packed bf16 hi/lo [c][p/2].
__global__ __launch_bounds__(512) void freq_kernel(const float* __restrict__ x) {
    __shared__ float sa[96 * 97];
    __shared__ float sc1[96], ss1[96], sc2[96], ss2[96];
    __shared__ unsigned char pidx[4][96];
    __shared__ float Gp[4][4][96][2];
    __shared__ float s2p[64][2];
    __shared__ float sF[32];
    __shared__ float sP[4][96][2];
    __shared__ float sMin[16], sMax[16];

    const int ch  = blockIdx.x;
    const int tid = threadIdx.x;

    if (ch < 48) g_FQM[ch * 512 + tid] = -INFINITY;   // init Fuse_Q_mask buffer

    if (tid < 96) {
        double th = 2.0 * 3.14159265358979323846 * (double)tid / 96.0;
        int m2 = (2 * tid) % 96;
        double th2 = 2.0 * 3.14159265358979323846 * (double)m2 / 96.0;
        sc1[tid] = (float)cos(th);
        ss1[tid] = (float)sin(th);
        sc2[tid] = (float)cos(th2);
        ss2[tid] = (float)sin(th2);
    }
    if (tid >= 128 && tid < 512) {
        int t = tid - 128;
        int k = t / 96, v = t - k * 96;
        int m = ((k - 2) * v) % 96; if (m < 0) m += 96;
        pidx[k][v] = (unsigned char)m;
    }

    const float4* xc4 = (const float4*)(x + (size_t)ch * HW);
    float lmin = INFINITY, lmax = -INFINITY;
    #pragma unroll
    for (int k = 0; k < 5; k++) {
        int i4 = k * 512 + tid;
        if (i4 < 2304) {
            float4 v = xc4[i4];
            float a0 = fabsf(v.x), a1 = fabsf(v.y);
            float a2 = fabsf(v.z), a3 = fabsf(v.w);
            int h = i4 / 24;
            int w = (i4 - h * 24) * 4;
            float* dst = sa + h * 97 + w;
            dst[0] = a0; dst[1] = a1; dst[2] = a2; dst[3] = a3;
            lmin = fminf(lmin, fminf(fminf(a0, a1), fminf(a2, a3)));
            lmax = fmaxf(lmax, fmaxf(fmaxf(a0, a1), fmaxf(a2, a3)));
        }
    }
    #pragma unroll
    for (int off = 16; off; off >>= 1) {
        lmin = fminf(lmin, __shfl_down_sync(0xffffffffu, lmin, off));
        lmax = fmaxf(lmax, __shfl_down_sync(0xffffffffu, lmax, off));
    }
    const int wid = tid >> 5, lane = tid & 31;
    if (lane == 0) { sMin[wid] = lmin; sMax[wid] = lmax; }
    __syncthreads();

    float mn = sMin[0], mx = sMax[0];
    #pragma unroll
    for (int j = 1; j < 16; j++) { mn = fminf(mn, sMin[j]); mx = fmaxf(mx, sMax[j]); }
    const float s255 = 255.0f / (mx - mn);

    if (tid < 384) {
        const int w  = tid >> 2;
        const int qh = tid & 3;
        const int h0 = qh * 24;
        float G0 = 0.f, G1r = 0.f, G1p = 0.f, G2r = 0.f, G2p = 0.f;
        #pragma unroll 4
        for (int j = 0; j < 24; j++) {
            int h = h0 + j;
            float q = floorf((sa[h * 97 + w] - mn) * s255);
            G0  += q;
            G1r += q * sc1[h]; G1p += q * ss1[h];
            G2r += q * sc2[h]; G2p += q * ss2[h];
        }
        Gp[qh][0][w][0] = G2r; Gp[qh][0][w][1] =  G2p;
        Gp[qh][1][w][0] = G1r; Gp[qh][1][w][1] =  G1p;
        Gp[qh][2][w][0] = G0;  Gp[qh][2][w][1] =  0.f;
        Gp[qh][3][w][0] = G1r; Gp[qh][3][w][1] = -G1p;
    }
    __syncthreads();

    if (tid < 64) {
        int coef = tid >> 2, q4 = tid & 3;
        int kr = coef >> 2, kc = coef & 3;
        float fr = 0.f, fi = 0.f;
        int w0 = q4 * 24;
        for (int w = w0; w < w0 + 24; w++) {
            float grw = Gp[0][kr][w][0] + Gp[1][kr][w][0]
                      + Gp[2][kr][w][0] + Gp[3][kr][w][0];
            float giw = Gp[0][kr][w][1] + Gp[1][kr][w][1]
                      + Gp[2][kr][w][1] + Gp[3][kr][w][1];
            int m = pidx[kc][w];
            float cc = sc1[m], ss = ss1[m];
            fr += grw * cc + giw * ss;
            fi += giw * cc - grw * ss;
        }
        s2p[tid][0] = fr;
        s2p[tid][1] = fi;
    }
    __syncthreads();
    if (tid < 32) {
        int coef = tid >> 1, ri = tid & 1;
        sF[coef * 2 + ri] = s2p[coef * 4][ri] + s2p[coef * 4 + 1][ri]
                          + s2p[coef * 4 + 2][ri] + s2p[coef * 4 + 3][ri];
    }
    __syncthreads();

    if (tid < 96) {
        int w = tid;
        #pragma unroll
        for (int kr = 0; kr < 4; kr++) {
            float pre = 0.f, pim = 0.f;
            #pragma unroll
            for (int kc = 0; kc < 4; kc++) {
                int m = pidx[kc][w];
                float fr = sF[2 * (kr * 4 + kc)], fi = sF[2 * (kr * 4 + kc) + 1];
                float cc = sc1[m], ss = ss1[m];
                pre += fr * cc - fi * ss;
                pim += fr * ss + fi * cc;
            }
            sP[kr][w][0] = pre;
            sP[kr][w][1] = pim;
        }
    }
    __syncthreads();

    const float inv = 1.0f / 9216.0f;
    uint2* fqh2 = (uint2*)g_FQh;
    uint2* fql2 = (uint2*)g_FQl;
    #pragma unroll
    for (int k = 0; k < 5; k++) {
        int i4 = k * 512 + tid;
        if (i4 < 2304) {
            int pix = i4 * 4;
            int h = pix / 96, w0 = pix - h * 96;
            float c1v = sc1[h], s1v = ss1[h];
            float c2v = sc2[h], s2v = ss2[h];
            float cr[4] = { c2v,  c1v, 1.f, c1v };
            float sr[4] = { -s2v, -s1v, 0.f, s1v };
            float vv[4];
            #pragma unroll
            for (int dw = 0; dw < 4; dw++) {
                float re = 0.f, im = 0.f;
                #pragma unroll
                for (int kr = 0; kr < 4; kr++) {
                    float pre = sP[kr][w0 + dw][0], pim = sP[kr][w0 + dw][1];
                    re += pre * cr[kr] - pim * sr[kr];
                    im += pre * sr[kr] + pim * cr[kr];
                }
                vv[dw] = sqrtf(re * re + im * im) * inv;
            }
            uint32_t ph0 = pack_bf2(vv[0], vv[1]);
            uint32_t ph1 = pack_bf2(vv[2], vv[3]);
            uint32_t pl0 = pack_bf2(vv[0] - bf_hi_val(vv[0]), vv[1] - bf_hi_val(vv[1]));
            uint32_t pl1 = pack_bf2(vv[2] - bf_hi_val(vv[2]), vv[3] - bf_hi_val(vv[3]));
            fqh2[(size_t)ch * 2304 + i4] = make_uint2(ph0, ph1);
            fql2[(size_t)ch * 2304 + i4] = make_uint2(pl0, pl1);
        }
    }
}

// ---------------------------------------------------------------------------
// Split-precision bf16 GEMM via mma.sync.m16n8k16 (HMMA tensor pipe).
// out[o,p] = sum_c W[o,c] X[c,p] + bias[o],  O=256, P=9216, K=256.
// CTA tile: M=128 x N=64, 4 K-phases of 64. cp.async double-buffered A;
// B staged sync (row-major [c][p], ldmatrix.x4.trans fragments).
// MODE 0 (Q): B from g_FQh/l (packed bf16).  MODE 1 (V): B from fp32 fuse,
// split inline (same bytes as packed path). 3 passes: AhBh + AhBl + AlBh.
// smem 92 KB -> 2 CTA/SM (184 <= 228 KB).
#define APITCH 36            // u32 per A row  (36%32=4 -> conflict-free LDS)
#define BPITCH 36            // u32 per B row  (144B; ldmatrix-clean)
#define ABUF   4608          // 128*36 u32 per A buffer
#define AH0_OFF 0
#define AL0_OFF 4608
#define AH1_OFF 9216
#define AL1_OFF 13824
#define BH_OFF  18432
#define BL_OFF  20736
#define SMEM_U32 23040       // 92160 bytes

template <int MODE>
__global__ __launch_bounds__(256, 2) void gemm_mma(
    const float* __restrict__ bias, float* __restrict__ out,
    const float* __restrict__ xf)
{
    extern __shared__ uint32_t su[];
    const int tid  = threadIdx.x;
    const int wid  = tid >> 5, lane = tid & 31;
    const int mw   = wid >> 2, nw = wid & 3;     // 2m x 4n warp grid
    const int gq   = lane >> 2, l4 = lane & 3;
    const int p0   = blockIdx.x * 64;
    const int o0   = blockIdx.y * 128;

    const uint32_t* Ah = (MODE == 0) ? g_Wh0 : g_Wh1;
    const uint32_t* Al = (MODE == 0) ? g_Wl0 : g_Wl1;

    // ldmatrix lane address offset (bytes within B tile), constant per lane.
    const int ltile = lane >> 3, lrow = lane & 7;
    const int lbyte = (((ltile & 1) << 3) + lrow) * 144
                    + ((nw << 4) + ((ltile >> 1) << 3)) * 2;
    const uint32_t sbase = (uint32_t)__cvta_generic_to_shared(su);
    const uint32_t baddr_h = sbase + BH_OFF * 4 + lbyte;
    const uint32_t baddr_l = sbase + BL_OFF * 4 + lbyte;

    // ---- prologue: cp.async A for phase 0 into buffer 0 -------------------
    #pragma unroll
    for (int f = tid; f < 1024; f += 256) {
        int o = f >> 3, q = f & 7;
        const void* gh = (const void*)(Ah + (size_t)(o0 + o) * 128 + q * 4);
        const void* gl = (const void*)(Al + (size_t)(o0 + o) * 128 + q * 4);
        cp_async16(sbase + (AH0_OFF + o * APITCH + q * 4) * 4, gh);
        cp_async16(sbase + (AL0_OFF + o * APITCH + q * 4) * 4, gl);
    }
    CP_ASYNC_COMMIT();

    float acc[4][2][4];
    #pragma unroll
    for (int mi = 0; mi < 4; mi++)
        #pragma unroll
        for (int ni = 0; ni < 2; ni++)
            #pragma unroll
            for (int r = 0; r < 4; r++) acc[mi][ni][r] = 0.f;

    #pragma unroll 1
    for (int kb = 0; kb < 4; kb++) {
        const int AOFF = (kb & 1) ? AH1_OFF : AH0_OFF;

        // ---- stage B (sync): 64 c-rows x 64 p, hi+lo ----------------------
        if (MODE == 0) {
            #pragma unroll
            for (int f = tid; f < 512; f += 256) {
                int c = f >> 3, q = f & 7;
                const uint4* gh = (const uint4*)(g_FQh + (size_t)(kb * 64 + c) * 4608 + (p0 >> 1));
                const uint4* gl = (const uint4*)(g_FQl + (size_t)(kb * 64 + c) * 4608 + (p0 >> 1));
                ((uint4*)(su + BH_OFF + c * BPITCH))[q] = gh[q];
                ((uint4*)(su + BL_OFF + c * BPITCH))[q] = gl[q];
            }
        } else {
            #pragma unroll
            for (int f = tid; f < 512; f += 256) {
                int c = f >> 3, q = f & 7;
                const float4* gx = (const float4*)(xf + (size_t)(kb * 64 + c) * HW + p0 + q * 8);
                float4 x0 = gx[0], x1 = gx[1];
                uint4 vh, vl;
                vh.x = pack_bf2(x0.x, x0.y); vh.y = pack_bf2(x0.z, x0.w);
                vh.z = pack_bf2(x1.x, x1.y); vh.w = pack_bf2(x1.z, x1.w);
                vl.x = pack_bf2(x0.x - bf_hi_val(x0.x), x0.y - bf_hi_val(x0.y));
                vl.y = pack_bf2(x0.z - bf_hi_val(x0.z), x0.w - bf_hi_val(x0.w));
                vl.z = pack_bf2(x1.x - bf_hi_val(x1.x), x1.y - bf_hi_val(x1.y));
                vl.w = pack_bf2(x1.z - bf_hi_val(x1.z), x1.w - bf_hi_val(x1.w));
                ((uint4*)(su + BH_OFF + c * BPITCH))[q] = vh;
                ((uint4*)(su + BL_OFF + c * BPITCH))[q] = vl;
            }
        }

        CP_ASYNC_WAIT0();        // phase-kb A landed
        __syncthreads();

        // ---- prefetch A for phase kb+1 into the other buffer --------------
        if (kb < 3) {
            const int AN = (kb & 1) ? AH0_OFF : AH1_OFF;
            #pragma unroll
            for (int f = tid; f < 1024; f += 256) {
                int o = f >> 3, q = f & 7;
                const void* gh = (const void*)(Ah + (size_t)(o0 + o) * 128 + (kb + 1) * 32 + q * 4);
                const void* gl = (const void*)(Al + (size_t)(o0 + o) * 128 + (kb + 1) * 32 + q * 4);
                cp_async16(sbase + (AN + o * APITCH + q * 4) * 4, gh);
                cp_async16(sbase + (AN + ABUF + o * APITCH + q * 4) * 4, gl);
            }
            CP_ASYNC_COMMIT();
        }

        // ---- compute: 4 k-steps of 16 -------------------------------------
        #pragma unroll 1
        for (int ks = 0; ks < 4; ks++) {
            const int k0w = ks * 8;
            uint32_t bh[2][2], bl[2][2];
            asm volatile(
                "ldmatrix.sync.aligned.m8n8.x4.trans.shared.b16 "
                "{%0,%1,%2,%3}, [%4];"
                : "=r"(bh[0][0]), "=r"(bh[0][1]), "=r"(bh[1][0]), "=r"(bh[1][1])
                : "r"(baddr_h + ks * 2304));
            asm volatile(
                "ldmatrix.sync.aligned.m8n8.x4.trans.shared.b16 "
                "{%0,%1,%2,%3}, [%4];"
                : "=r"(bl[0][0]), "=r"(bl[0][1]), "=r"(bl[1][0]), "=r"(bl[1][1])
                : "r"(baddr_l + ks * 2304));
            #pragma unroll
            for (int mi = 0; mi < 4; mi++) {
                int row = mw * 64 + mi * 16 + gq;
                int base = AOFF + row * APITCH + k0w + l4;
                uint32_t ah[4], al[4];
                ah[0] = su[base];
                ah[1] = su[base + 8 * APITCH];
                ah[2] = su[base + 4];
                ah[3] = su[base + 8 * APITCH + 4];
                al[0] = su[base + ABUF];
                al[1] = su[base + ABUF + 8 * APITCH];
                al[2] = su[base + ABUF + 4];
                al[3] = su[base + ABUF + 8 * APITCH + 4];
                #pragma unroll
                for (int ni = 0; ni < 2; ni++) {
                    mma16816(acc[mi][ni], ah, bh[ni]);
                    mma16816(acc[mi][ni], ah, bl[ni]);
                    mma16816(acc[mi][ni], al, bh[ni]);
                }
            }
        }
        __syncthreads();
    }

    // ---- epilogue --------------------------------------------------------
    if (MODE == 1) {
        #pragma unroll
        for (int mi = 0; mi < 4; mi++) {
            int o = o0 + mw * 64 + mi * 16 + gq;
            float b0 = bias[o], b1 = bias[o + 8];
            #pragma unroll
            for (int ni = 0; ni < 2; ni++) {
                int p = p0 + nw * 16 + ni * 8 + l4 * 2;
                float2 v0 = { acc[mi][ni][0] + b0, acc[mi][ni][1] + b0 };
                float2 v1 = { acc[mi][ni][2] + b1, acc[mi][ni][3] + b1 };
                *(float2*)(out + (size_t)o * HW + p)       = v0;
                *(float2*)(out + (size_t)(o + 8) * HW + p) = v1;
            }
        }
    } else {
        // row class (o mod 8) == gq for every acc this thread holds
        float* red = (float*)su;                 // 8 x 64
        for (int t = tid; t < 512; t += 256) red[t] = -INFINITY;
        __syncthreads();
        float bo[4][2];
        #pragma unroll
        for (int mi = 0; mi < 4; mi++) {
            int o = o0 + mw * 64 + mi * 16 + gq;
            bo[mi][0] = bias[o];
            bo[mi][1] = bias[o + 8];
        }
        #pragma unroll
        for (int ni = 0; ni < 2; ni++) {
            #pragma unroll
            for (int l = 0; l < 2; l++) {
                int col = nw * 16 + ni * 8 + l4 * 2 + l;
                float m = -INFINITY;
                #pragma unroll
                for (int mi = 0; mi < 4; mi++) {
                    m = fmaxf(m, acc[mi][ni][l]     + bo[mi][0]);
                    m = fmaxf(m, acc[mi][ni][2 + l] + bo[mi][1]);
                }
                atomicMaxFloat(&red[gq * 64 + col], m);
            }
        }
        __syncthreads();
        for (int t = tid; t < 512; t += 256) {
            int cls = t >> 6, col = t & 63;
            unsigned idx = ((unsigned)cls * 9216u + (unsigned)(p0 + col)) % 24576u;
            atomicMaxFloat(&g_FQM[idx], red[t]);
        }
    }
}

// ---------------------------------------------------------------------------
// out[e] *= (1 + g_FQM[e % 24576]), float4.
__global__ __launch_bounds__(256) void mask_epilogue(float* __restrict__ out) {
    unsigned v = blockIdx.x * 256u + threadIdx.x;
    unsigned idx = (v * 4u) % 24576u;
    float4 o = ((float4*)out)[v];
    float4 m = *(const float4*)&g_FQM[idx];
    o.x *= (1.0f + m.x);
    o.y *= (1.0f + m.y);
    o.z *= (1.0f + m.z);
    o.w *= (1.0f + m.w);
    ((float4*)out)[v] = o;
}

// ---------------------------------------------------------------------------
extern "C" void kernel_launch(void* const* d_in, const int* in_sizes, int n_in,
                              void* d_out, int out_size) {
    const float* fuse = (const float*)d_in[0];
    const float* Wq   = (const float*)d_in[1];
    const float* bq   = (const float*)d_in[2];
    // d_in[3] (Wk), d_in[4] (bk): dead code — softmax over batch axis of size 1
    const float* Wv   = (const float*)d_in[5];
    const float* bv   = (const float*)d_in[6];
    float* out = (float*)d_out;

    cudaFuncSetAttribute(gemm_mma<0>,
        cudaFuncAttributeMaxDynamicSharedMemorySize, SMEM_U32 * 4);
    cudaFuncSetAttribute(gemm_mma<1>,
        cudaFuncAttributeMaxDynamicSharedMemorySize, SMEM_U32 * 4);

    static cudaStream_t s1 = nullptr;
    static cudaEvent_t evRoot = nullptr, evW = nullptr, evG0 = nullptr;
    if (s1 == nullptr) {
        cudaStreamCreateWithFlags(&s1, cudaStreamNonBlocking);
        cudaEventCreateWithFlags(&evRoot, cudaEventDisableTiming);
        cudaEventCreateWithFlags(&evW, cudaEventDisableTiming);
        cudaEventCreateWithFlags(&evG0, cudaEventDisableTiming);
    }

    // Fork side stream.
    cudaEventRecord(evRoot, 0);
    cudaStreamWaitEvent(s1, evRoot, 0);

    // Main: W convert -> V-GEMM (reads fuse fp32 directly; overlaps freq).
    convert_w<<<128, 256>>>(Wq, Wv);
    cudaEventRecord(evW, 0);
    gemm_mma<1><<<dim3(144, 2), 256, SMEM_U32 * 4>>>(bv, out, fuse);

    // Side: freq -> Q-GEMM (overlaps V-GEMM tail).
    freq_kernel<<<C_DIM, 512, 0, s1>>>(fuse);          // also inits g_FQM
    cudaStreamWaitEvent(s1, evW, 0);
    gemm_mma<0><<<dim3(144, 2), 256, SMEM_U32 * 4, s1>>>(bq, nullptr, nullptr);
    cudaEventRecord(evG0, s1);

    // Join: mask needs out (main) + g_FQM (side).
    cudaStreamWaitEvent(0, evG0, 0);
    mask_epilogue<<<NPIX / 4 / 256, 256>>>(out);
}